// round 9
// baseline (speedup 1.0000x reference)
#include <cuda_runtime.h>

// PointNetKnnInterpolator: fused edge-MLP + segment_max.
//   E = NY*8 edges; per edge:
//     h   = [x[x_idx], pos_x[x_idx]-pos_y[y_idx]]           (67)
//     net = relu(h)@W0a + b0a
//     dx  = relu(net)@W1a + b1a
//     h2  = h@Wsa + dx
//     net2= relu(h2)@W0b + b0b
//     h3  = h2 + relu(net2)@W1b + b1b
//   out[y] = max over the 8 edges of y of h3.
//
// Block = 16 y's = 128 edges. All weights staged in smem, 5 chained
// 128x64 fp32 GEMMs, register-tile 4 edges x 8 feats per thread.

#define THREADS 256
#define YS_PER_BLOCK 16
#define EDGES 128

// smem float offsets
#define OFF_WA   0
#define OFF_W1A  (68*64)
#define OFF_WS   (132*64)
#define OFF_W0B  (200*64)
#define OFF_W1B  (264*64)
#define OFF_BIAS (328*64)
#define OFF_H    (OFF_BIAS + 256)
#define OFF_BUF1 (OFF_H + 128*68)
#define OFF_BUF2 (OFF_BUF1 + 128*64)
#define SMEM_FLOATS (OFF_BUF2 + 128*64)
#define SMEM_BYTES (SMEM_FLOATS * 4)

template<int KDIM, int LDA, bool RELUA>
__device__ __forceinline__ void gemm_acc(const float* __restrict__ As,
                                         const float* __restrict__ Ws,
                                         float (&acc)[4][8], int ty, int tx)
{
#pragma unroll 2
    for (int k0 = 0; k0 < KDIM; k0 += 4) {
        float a[4][4];
#pragma unroll
        for (int r = 0; r < 4; r++) {
            float4 v = *(const float4*)(As + (4 * ty + r) * LDA + k0);
            a[r][0] = v.x; a[r][1] = v.y; a[r][2] = v.z; a[r][3] = v.w;
            if (RELUA) {
#pragma unroll
                for (int q = 0; q < 4; q++) a[r][q] = fmaxf(a[r][q], 0.0f);
            }
        }
#pragma unroll
        for (int kk = 0; kk < 4; kk++) {
            float4 w0 = *(const float4*)(Ws + (k0 + kk) * 64 + 8 * tx);
            float4 w1 = *(const float4*)(Ws + (k0 + kk) * 64 + 8 * tx + 4);
            float w[8] = {w0.x, w0.y, w0.z, w0.w, w1.x, w1.y, w1.z, w1.w};
#pragma unroll
            for (int r = 0; r < 4; r++)
#pragma unroll
                for (int c = 0; c < 8; c++)
                    acc[r][c] = fmaf(a[r][kk], w[c], acc[r][c]);
        }
    }
}

__device__ __forceinline__ void store_tile(float* __restrict__ Bf,
                                           const float (&acc)[4][8], int ty, int tx)
{
#pragma unroll
    for (int r = 0; r < 4; r++) {
        float4* p = (float4*)(Bf + (4 * ty + r) * 64 + 8 * tx);
        p[0] = make_float4(acc[r][0], acc[r][1], acc[r][2], acc[r][3]);
        p[1] = make_float4(acc[r][4], acc[r][5], acc[r][6], acc[r][7]);
    }
}

__device__ __forceinline__ void init_bias(float (&acc)[4][8],
                                          const float* __restrict__ bias, int tx)
{
    float4 b0 = *(const float4*)(bias + 8 * tx);
    float4 b1 = *(const float4*)(bias + 8 * tx + 4);
    float b[8] = {b0.x, b0.y, b0.z, b0.w, b1.x, b1.y, b1.z, b1.w};
#pragma unroll
    for (int r = 0; r < 4; r++)
#pragma unroll
        for (int c = 0; c < 8; c++) acc[r][c] = b[c];
}

__device__ __forceinline__ void init_buf(float (&acc)[4][8],
                                         const float* __restrict__ Bf, int ty, int tx)
{
#pragma unroll
    for (int r = 0; r < 4; r++) {
        float4 v0 = *(const float4*)(Bf + (4 * ty + r) * 64 + 8 * tx);
        float4 v1 = *(const float4*)(Bf + (4 * ty + r) * 64 + 8 * tx + 4);
        acc[r][0] = v0.x; acc[r][1] = v0.y; acc[r][2] = v0.z; acc[r][3] = v0.w;
        acc[r][4] = v1.x; acc[r][5] = v1.y; acc[r][6] = v1.z; acc[r][7] = v1.w;
    }
}

__global__ void __launch_bounds__(THREADS, 1)
pointnet_knn_kernel(const float* __restrict__ x,
                    const float* __restrict__ pos_x,
                    const float* __restrict__ pos_y,
                    const int*   __restrict__ x_idx,
                    const int*   __restrict__ y_idx,
                    const float* __restrict__ W0a, const float* __restrict__ b0a,
                    const float* __restrict__ W1a, const float* __restrict__ b1a,
                    const float* __restrict__ Wsa,
                    const float* __restrict__ W0b, const float* __restrict__ b0b,
                    const float* __restrict__ W1b, const float* __restrict__ b1b,
                    float* __restrict__ out, int NY, int E)
{
    extern __shared__ float s[];
    const int tid = threadIdx.x;

    // ---- stage weights into smem (float4 strided copies) ----
    auto cp = [&](float* dst, const float* src, int nf) {
        const float4* s4 = (const float4*)src;
        float4* d4 = (float4*)dst;
        for (int idx = tid; idx < (nf >> 2); idx += THREADS) d4[idx] = s4[idx];
    };
    cp(s + OFF_WA,  W0a, 67 * 64);
    cp(s + OFF_W1A, W1a, 64 * 64);
    cp(s + OFF_WS,  Wsa, 67 * 64);
    cp(s + OFF_W0B, W0b, 64 * 64);
    cp(s + OFF_W1B, W1b, 64 * 64);
    if (tid < 64) {
        s[OFF_WA + 67 * 64 + tid] = 0.0f;   // zero-pad K row 67
        s[OFF_WS + 67 * 64 + tid] = 0.0f;
        s[OFF_BIAS +       tid] = b0a[tid];
        s[OFF_BIAS +  64 + tid] = b1a[tid];
        s[OFF_BIAS + 128 + tid] = b0b[tid];
        s[OFF_BIAS + 192 + tid] = b1b[tid];
    }

    // ---- gather H (128 edges x 68) : 2 threads per edge ----
    {
        const int el = tid >> 1, half = tid & 1;
        const int ge = blockIdx.x * EDGES + el;
        float* hr = s + OFF_H + el * 68;
        if (ge < E) {
            const int i = x_idx[ge];
            const float4* xr = (const float4*)(x + (size_t)i * 64) + half * 8;
            float4* hd = (float4*)(hr + half * 32);
#pragma unroll
            for (int c = 0; c < 8; c++) hd[c] = xr[c];
            if (half) {
                const int j = y_idx[ge];
                hr[64] = pos_x[3 * (size_t)i + 0] - pos_y[3 * (size_t)j + 0];
                hr[65] = pos_x[3 * (size_t)i + 1] - pos_y[3 * (size_t)j + 1];
                hr[66] = pos_x[3 * (size_t)i + 2] - pos_y[3 * (size_t)j + 2];
                hr[67] = 0.0f;
            }
        } else {
            float4* hd = (float4*)(hr + half * 32);
#pragma unroll
            for (int c = 0; c < 8; c++) hd[c] = make_float4(0.f, 0.f, 0.f, 0.f);
            if (half) { hr[64] = hr[65] = hr[66] = hr[67] = 0.0f; }
        }
    }
    __syncthreads();

    const int ty = tid >> 3;   // 0..31 -> edges 4*ty..4*ty+3
    const int tx = tid & 7;    // 0..7  -> feats 8*tx..8*tx+7
    const float* Hs = s + OFF_H;
    float* B1 = s + OFF_BUF1;
    float* B2 = s + OFF_BUF2;
    float acc[4][8];

    // G1: net = relu(H)@W0a + b0a  -> B1
    init_bias(acc, s + OFF_BIAS, tx);
    gemm_acc<68, 68, true>(Hs, s + OFF_WA, acc, ty, tx);
    store_tile(B1, acc, ty, tx);
    __syncthreads();

    // G2: dx = relu(net)@W1a + b1a -> B2
    init_bias(acc, s + OFF_BIAS + 64, tx);
    gemm_acc<64, 64, true>(B1, s + OFF_W1A, acc, ty, tx);
    store_tile(B2, acc, ty, tx);
    __syncthreads();

    // G3: h2 = H@Wsa + dx -> B1
    init_buf(acc, B2, ty, tx);
    gemm_acc<68, 68, false>(Hs, s + OFF_WS, acc, ty, tx);
    store_tile(B1, acc, ty, tx);
    __syncthreads();

    // G4: net2 = relu(h2)@W0b + b0b -> B2
    init_bias(acc, s + OFF_BIAS + 128, tx);
    gemm_acc<64, 64, true>(B1, s + OFF_W0B, acc, ty, tx);
    store_tile(B2, acc, ty, tx);
    __syncthreads();

    // G5: h3 = h2 + relu(net2)@W1b + b1b  (stays in registers)
    init_buf(acc, B1, ty, tx);
    {
        float4 b0 = *(const float4*)(s + OFF_BIAS + 192 + 8 * tx);
        float4 b1 = *(const float4*)(s + OFF_BIAS + 192 + 8 * tx + 4);
        float b[8] = {b0.x, b0.y, b0.z, b0.w, b1.x, b1.y, b1.z, b1.w};
#pragma unroll
        for (int r = 0; r < 4; r++)
#pragma unroll
            for (int c = 0; c < 8; c++) acc[r][c] += b[c];
    }
    gemm_acc<64, 64, true>(B2, s + OFF_W1B, acc, ty, tx);

    // ---- segment max: 8 edges per y = this thread's 4 edges + partner (ty^1) ----
    float m[8];
#pragma unroll
    for (int c = 0; c < 8; c++)
        m[c] = fmaxf(fmaxf(acc[0][c], acc[1][c]), fmaxf(acc[2][c], acc[3][c]));
#pragma unroll
    for (int c = 0; c < 8; c++)
        m[c] = fmaxf(m[c], __shfl_xor_sync(0xffffffffu, m[c], 8));

    if ((ty & 1) == 0) {
        const int y = blockIdx.x * YS_PER_BLOCK + (ty >> 1);
        if (y < NY) {
            float4* o = (float4*)(out + (size_t)y * 64 + 8 * tx);
            o[0] = make_float4(m[0], m[1], m[2], m[3]);
            o[1] = make_float4(m[4], m[5], m[6], m[7]);
        }
    }
}

extern "C" void kernel_launch(void* const* d_in, const int* in_sizes, int n_in,
                              void* d_out, int out_size)
{
    const float* x     = (const float*)d_in[0];
    const float* pos_x = (const float*)d_in[1];
    const float* pos_y = (const float*)d_in[2];
    const int*   x_idx = (const int*)d_in[3];
    const int*   y_idx = (const int*)d_in[4];
    const float* W0a = (const float*)d_in[5];
    const float* b0a = (const float*)d_in[6];
    const float* W1a = (const float*)d_in[7];
    const float* b1a = (const float*)d_in[8];
    const float* Wsa = (const float*)d_in[9];
    const float* W0b = (const float*)d_in[10];
    const float* b0b = (const float*)d_in[11];
    const float* W1b = (const float*)d_in[12];
    const float* b1b = (const float*)d_in[13];
    float* out = (float*)d_out;

    const int NY = in_sizes[2] / 3;     // pos_y is (NY, 3)
    const int E  = in_sizes[3];         // x_idx is (NY*K,)

    cudaFuncSetAttribute(pointnet_knn_kernel,
                         cudaFuncAttributeMaxDynamicSharedMemorySize, SMEM_BYTES);

    const int blocks = (NY + YS_PER_BLOCK - 1) / YS_PER_BLOCK;
    pointnet_knn_kernel<<<blocks, THREADS, SMEM_BYTES>>>(
        x, pos_x, pos_y, x_idx, y_idx,
        W0a, b0a, W1a, b1a, Wsa, W0b, b0b, W1b, b1b,
        out, NY, E);
}

// round 10
// speedup vs baseline: 1.5539x; 1.5539x over previous
#include <cuda_runtime.h>

// PointNetKnnInterpolator: fused edge-MLP + segment_max, fp32x2 packed FMA.
//
// Block = 32 y's = 256 edges, 512 threads (16 warps/SM).
// Thread tile: 4 edges (rows 4*ty..4*ty+3) x 8 feats (8*tx..8*tx+7),
// accumulators packed as f32x2 along the feature axis.
//
// Shared memory (floats), total 224256 bytes:
//   5 weight matrices (W swizzled: row chunk 8tx+4h+j -> pos 4tx+32h+j)
//   biases, H (256x68, chunk-XOR swizzled), B1 (256x68, same swizzle)
// Buffer reuse: dx lives in registers (G2 acc carries into G3);
// net2 is stored into the dead H buffer for G5.

#define THREADS 512
#define EDGES 256
#define YPB 32

#define OFF_WA   0
#define OFF_W1A  (68*64)
#define OFF_WS   (132*64)
#define OFF_W0B  (200*64)
#define OFF_W1B  (264*64)
#define OFF_BIAS (328*64)
#define OFF_H    (OFF_BIAS + 256)
#define OFF_B1   (OFF_H + 256*68)
#define SMEM_FLOATS (OFF_B1 + 256*68)
#define SMEM_BYTES (SMEM_FLOATS * 4)   // 224256

typedef unsigned long long u64;

__device__ __forceinline__ u64 dup2(float a) {
    u64 r;
    asm("mov.b64 %0, {%1, %1};" : "=l"(r) : "f"(a));
    return r;
}
__device__ __forceinline__ void fma2(u64& acc, u64 a, u64 b) {
    asm("fma.rn.f32x2 %0, %1, %2, %3;" : "=l"(acc) : "l"(a), "l"(b), "l"(acc));
}
__device__ __forceinline__ u64 add2(u64 a, u64 b) {
    u64 r;
    asm("add.rn.f32x2 %0, %1, %2;" : "=l"(r) : "l"(a), "l"(b));
    return r;
}
__device__ __forceinline__ float2 unpack2(u64 v) {
    float2 f;
    asm("mov.b64 {%0, %1}, %2;" : "=f"(f.x), "=f"(f.y) : "l"(v));
    return f;
}

// One K-chunk (4 k-values) of the GEMM. coff = float offset of this chunk
// within the A row (swizzle already applied by caller). wk = Ws row base.
template<bool RELUA>
__device__ __forceinline__ void gemm_chunk(const float* __restrict__ arow,
                                           const float* __restrict__ wk,
                                           int coff, u64 (&acc)[4][4])
{
    float a[4][4];
#pragma unroll
    for (int r = 0; r < 4; r++) {
        float4 v = *(const float4*)(arow + r * 68 + coff);
        a[r][0] = v.x; a[r][1] = v.y; a[r][2] = v.z; a[r][3] = v.w;
        if (RELUA) {
#pragma unroll
            for (int q = 0; q < 4; q++) a[r][q] = fmaxf(a[r][q], 0.0f);
        }
    }
#pragma unroll
    for (int kk = 0; kk < 4; kk++) {
        ulonglong2 w01 = *(const ulonglong2*)(wk + kk * 64);
        ulonglong2 w23 = *(const ulonglong2*)(wk + kk * 64 + 32);
        u64 W0 = w01.x, W1 = w01.y, W2 = w23.x, W3 = w23.y;
#pragma unroll
        for (int r = 0; r < 4; r++) {
            u64 a2 = dup2(a[r][kk]);
            fma2(acc[r][0], a2, W0);
            fma2(acc[r][1], a2, W1);
            fma2(acc[r][2], a2, W2);
            fma2(acc[r][3], a2, W3);
        }
    }
}

// Full GEMM: 16 swizzled chunks (+ optional tail chunk 16, unswizzled).
template<bool RELUA, bool TAIL>
__device__ __forceinline__ void gemm_f32x2(const float* __restrict__ As,
                                           const float* __restrict__ Ws,
                                           u64 (&acc)[4][4],
                                           int rowbase, int key, int tx)
{
    const float* arow = As + rowbase * 68;
    const float* wb = Ws + (tx << 2);
#pragma unroll 2
    for (int c = 0; c < 16; c++) {
        gemm_chunk<RELUA>(arow, wb + (c << 2) * 64, (c ^ key) << 2, acc);
    }
    if (TAIL) {
        gemm_chunk<RELUA>(arow, wb + (16 << 2) * 64, 64, acc);
    }
}

__device__ __forceinline__ void init_bias(u64 (&acc)[4][4],
                                          const float* __restrict__ bias, int tx)
{
    ulonglong2 b01 = *(const ulonglong2*)(bias + 8 * tx);
    ulonglong2 b23 = *(const ulonglong2*)(bias + 8 * tx + 4);
#pragma unroll
    for (int r = 0; r < 4; r++) {
        acc[r][0] = b01.x; acc[r][1] = b01.y;
        acc[r][2] = b23.x; acc[r][3] = b23.y;
    }
}

__device__ __forceinline__ void store_tile(float* __restrict__ Bf,
                                           const u64 (&acc)[4][4],
                                           int rowbase, int key, int tx)
{
    const int p0 = ((2 * tx) ^ key) << 2;
    const int p1 = ((2 * tx + 1) ^ key) << 2;
#pragma unroll
    for (int r = 0; r < 4; r++) {
        float* rowp = Bf + (rowbase + r) * 68;
        *(ulonglong2*)(rowp + p0) = make_ulonglong2(acc[r][0], acc[r][1]);
        *(ulonglong2*)(rowp + p1) = make_ulonglong2(acc[r][2], acc[r][3]);
    }
}

__global__ void __launch_bounds__(THREADS, 1)
pointnet_knn_kernel(const float* __restrict__ x,
                    const float* __restrict__ pos_x,
                    const float* __restrict__ pos_y,
                    const int*   __restrict__ x_idx,
                    const int*   __restrict__ y_idx,
                    const float* __restrict__ W0a, const float* __restrict__ b0a,
                    const float* __restrict__ W1a, const float* __restrict__ b1a,
                    const float* __restrict__ Wsa,
                    const float* __restrict__ W0b, const float* __restrict__ b0b,
                    const float* __restrict__ W1b, const float* __restrict__ b1b,
                    float* __restrict__ out, int NY, int E)
{
    extern __shared__ float s[];
    const int tid = threadIdx.x;

    // ---- stage weights (swizzled: src chunk g of row k -> pos (g>>1)+8*(g&1)) ----
    auto cpw = [&](float* dst, const float* src, int rows) {
        const int n4 = rows * 16;
        const float4* s4 = (const float4*)src;
        float4* d4 = (float4*)dst;
        for (int i = tid; i < n4; i += THREADS) {
            const int k = i >> 4, g = i & 15;
            d4[(k << 4) + (g >> 1) + ((g & 1) << 3)] = s4[i];
        }
    };
    cpw(s + OFF_WA,  W0a, 67);
    cpw(s + OFF_W1A, W1a, 64);
    cpw(s + OFF_WS,  Wsa, 67);
    cpw(s + OFF_W0B, W0b, 64);
    cpw(s + OFF_W1B, W1b, 64);
    if (tid < 64) {
        s[OFF_WA + 67 * 64 + tid] = 0.0f;   // zero-pad k=67 row
        s[OFF_WS + 67 * 64 + tid] = 0.0f;
        s[OFF_BIAS +       tid] = b0a[tid];
        s[OFF_BIAS +  64 + tid] = b1a[tid];
        s[OFF_BIAS + 128 + tid] = b0b[tid];
        s[OFF_BIAS + 192 + tid] = b1b[tid];
    }

    // ---- gather H (256 edges x 68), chunk-XOR swizzled, 2 threads/edge ----
    {
        const int el = tid >> 1, half = tid & 1;
        const int ge = blockIdx.x * EDGES + el;
        const int keyE = (el >> 3) & 1;
        float* hr = s + OFF_H + el * 68;
        if (ge < E) {
            const int i = x_idx[ge];
            const float4* xr = (const float4*)(x + (size_t)i * 64) + half * 8;
#pragma unroll
            for (int c2 = 0; c2 < 8; c2++) {
                const int chunk = 8 * half + c2;
                *(float4*)(hr + (((chunk) ^ keyE) << 2)) = xr[c2];
            }
            if (half) {
                const int j = y_idx[ge];
                hr[64] = pos_x[3 * (size_t)i + 0] - pos_y[3 * (size_t)j + 0];
                hr[65] = pos_x[3 * (size_t)i + 1] - pos_y[3 * (size_t)j + 1];
                hr[66] = pos_x[3 * (size_t)i + 2] - pos_y[3 * (size_t)j + 2];
                hr[67] = 0.0f;
            }
        } else {
            const float4 z = make_float4(0.f, 0.f, 0.f, 0.f);
#pragma unroll
            for (int c2 = 0; c2 < 8; c2++)
                *(float4*)(hr + ((((8 * half + c2)) ^ keyE) << 2)) = z;
            if (half) { hr[64] = hr[65] = hr[66] = hr[67] = 0.0f; }
        }
    }
    __syncthreads();

    const int ty = tid >> 3;          // 0..63  -> edges 4*ty..4*ty+3
    const int tx = tid & 7;           // 0..7   -> feats 8*tx..8*tx+7
    const int rowbase = 4 * ty;
    const int key = (ty >> 1) & 1;    // swizzle key, constant per thread
    const float* Hs = s + OFF_H;
    float* B1 = s + OFF_B1;
    u64 acc[4][4];

    // G1: net = relu(H)@W0a + b0a -> B1
    init_bias(acc, s + OFF_BIAS, tx);
    gemm_f32x2<true, true>(Hs, s + OFF_WA, acc, rowbase, key, tx);
    store_tile(B1, acc, rowbase, key, tx);
    __syncthreads();

    // G2: dx = relu(net)@W1a + b1a   (stays in acc)
    init_bias(acc, s + OFF_BIAS + 64, tx);
    gemm_f32x2<true, false>(B1, s + OFF_W1A, acc, rowbase, key, tx);
    __syncthreads();                  // all reads of B1(net) done

    // G3: h2 = dx + H@Wsa -> B1
    gemm_f32x2<false, true>(Hs, s + OFF_WS, acc, rowbase, key, tx);
    store_tile(B1, acc, rowbase, key, tx);
    __syncthreads();

    // G4: net2 = relu(h2)@W0b + b0b -> stored into H (dead)
    init_bias(acc, s + OFF_BIAS + 128, tx);
    gemm_f32x2<true, false>(B1, s + OFF_W0B, acc, rowbase, key, tx);
    store_tile(s + OFF_H, acc, rowbase, key, tx);
    __syncthreads();

    // G5: h3 = (h2 + b1b) + relu(net2)@W1b
    {
        ulonglong2 b01 = *(const ulonglong2*)(s + OFF_BIAS + 192 + 8 * tx);
        ulonglong2 b23 = *(const ulonglong2*)(s + OFF_BIAS + 192 + 8 * tx + 4);
        const int p0 = ((2 * tx) ^ key) << 2;
        const int p1 = ((2 * tx + 1) ^ key) << 2;
#pragma unroll
        for (int r = 0; r < 4; r++) {
            const float* rowp = B1 + (rowbase + r) * 68;
            ulonglong2 qa = *(const ulonglong2*)(rowp + p0);
            ulonglong2 qb = *(const ulonglong2*)(rowp + p1);
            acc[r][0] = add2(qa.x, b01.x);
            acc[r][1] = add2(qa.y, b01.y);
            acc[r][2] = add2(qb.x, b23.x);
            acc[r][3] = add2(qb.y, b23.y);
        }
    }
    gemm_f32x2<true, false>(s + OFF_H, s + OFF_W1B, acc, rowbase, key, tx);

    // ---- segment max: 8 edges/y = this thread's 4 edges + partner ty^1 ----
    float m[8];
#pragma unroll
    for (int p = 0; p < 4; p++) {
        float2 v0 = unpack2(acc[0][p]);
        float2 v1 = unpack2(acc[1][p]);
        float2 v2 = unpack2(acc[2][p]);
        float2 v3 = unpack2(acc[3][p]);
        m[2 * p + 0] = fmaxf(fmaxf(v0.x, v1.x), fmaxf(v2.x, v3.x));
        m[2 * p + 1] = fmaxf(fmaxf(v0.y, v1.y), fmaxf(v2.y, v3.y));
    }
#pragma unroll
    for (int c = 0; c < 8; c++)
        m[c] = fmaxf(m[c], __shfl_xor_sync(0xffffffffu, m[c], 8));

    if ((ty & 1) == 0) {
        const int y = blockIdx.x * YPB + (ty >> 1);
        if (y < NY) {
            float4* o = (float4*)(out + (size_t)y * 64 + 8 * tx);
            o[0] = make_float4(m[0], m[1], m[2], m[3]);
            o[1] = make_float4(m[4], m[5], m[6], m[7]);
        }
    }
}

extern "C" void kernel_launch(void* const* d_in, const int* in_sizes, int n_in,
                              void* d_out, int out_size)
{
    const float* x     = (const float*)d_in[0];
    const float* pos_x = (const float*)d_in[1];
    const float* pos_y = (const float*)d_in[2];
    const int*   x_idx = (const int*)d_in[3];
    const int*   y_idx = (const int*)d_in[4];
    const float* W0a = (const float*)d_in[5];
    const float* b0a = (const float*)d_in[6];
    const float* W1a = (const float*)d_in[7];
    const float* b1a = (const float*)d_in[8];
    const float* Wsa = (const float*)d_in[9];
    const float* W0b = (const float*)d_in[10];
    const float* b0b = (const float*)d_in[11];
    const float* W1b = (const float*)d_in[12];
    const float* b1b = (const float*)d_in[13];
    float* out = (float*)d_out;

    const int NY = in_sizes[2] / 3;   // pos_y is (NY, 3)
    const int E  = in_sizes[3];       // x_idx is (NY*K,)

    cudaFuncSetAttribute(pointnet_knn_kernel,
                         cudaFuncAttributeMaxDynamicSharedMemorySize, SMEM_BYTES);

    const int blocks = (NY + YPB - 1) / YPB;
    pointnet_knn_kernel<<<blocks, THREADS, SMEM_BYTES>>>(
        x, pos_x, pos_y, x_idx, y_idx,
        W0a, b0a, W1a, b1a, Wsa, W0b, b0b, W1b, b1b,
        out, NY, E);
}